// round 9
// baseline (speedup 1.0000x reference)
#include <cuda_runtime.h>

// CRF forward loss: B=1024, T=512, K=32.
// inputs: emissions f32 [B,T,K], tags i32 [B,T], mask int32 [B,T], trans f32 [K,K]
// output: scalar f32 loss = mean_b( log_z - em_score - tr_score )
//
// R9: linear-space recurrence. Keep p_j = exp(alpha_j - off), offset in cacc.
//   step:  s_j = sum_i p_i * E[i][j]  (shuffle dot, E=exp(trans) in regs)
//          p'_j = s_j * q_{t,j},  q = exp(em) precomputed in prefetch ring
//   -> no exp/log/broadcast in the per-step chain.
//   Renorm once per 4-step block by lane0's p sampled at block START
//   (shuffle/rcp/log overlap the dots; exact identity, mask-safe).
//   Path scores computed lane-parallel per 32-step chunk (1 LDG gather +
//   1 LDS gather + 1 ballot), removing 3 shuffles/step.

#define FULLM 0xffffffffu

constexpr int Bc = 1024;
constexpr int Tc = 512;
constexpr int Kc = 32;

__device__ float g_partial[Bc];

__global__ void __launch_bounds__(256, 1)
crf_forward(const float* __restrict__ em,
            const int* __restrict__ tags,
            const int* __restrict__ mask,
            const float* __restrict__ trans)
{
    __shared__ float tr_s[Kc * Kc];

    const int lane = threadIdx.x & 31;
    const int wid  = threadIdx.x >> 5;

    for (int i = threadIdx.x; i < Kc * Kc; i += blockDim.x)
        tr_s[i] = trans[i];
    __syncthreads();

    const int b = blockIdx.x * 8 + wid;

    // lane j holds column j of E = exp(transitions)
    float E[Kc];
#pragma unroll
    for (int i = 0; i < Kc; i++)
        E[i] = __expf(tr_s[i * Kc + lane]);

    const float* emB = em   + (size_t)b * Tc * Kc;
    const int*   tgB = tags + (size_t)b * Tc;
    const int*   mB  = mask + (size_t)b * Tc;

    // prefetch ring holds q = exp(em) for rows t..t+3
    float nxt0 = __expf(emB[0 * Kc + lane]);
    float nxt1 = __expf(emB[1 * Kc + lane]);
    float nxt2 = __expf(emB[2 * Kc + lane]);
    float nxt3 = __expf(emB[3 * Kc + lane]);

    // ---- t = 0 init: alpha0 = em[0] -> p = q0 / q0[0], cacc = em[0][0] ----
    float q00  = __shfl_sync(FULLM, nxt0, 0);
    float cacc = __logf(q00);
    float p    = nxt0 * __fdividef(1.0f, q00);

    float escore = 0.f, tscore = 0.f;
    int   tg_carry = 0;

    for (int ch = 0; ch < Tc / 32; ch++) {
        // ---- lane-parallel path scores for this 32-step chunk ----
        const int t_l = ch * 32 + lane;
        int tg = tgB[t_l];
        int mk = mB[t_l];
        unsigned mbits = __ballot_sync(FULLM, mk != 0);
        int tp = __shfl_up_sync(FULLM, tg, 1);
        if (lane == 0) tp = tg_carry;
        tg_carry = __shfl_sync(FULLM, tg, 31);
        float emtag = emB[(size_t)t_l * Kc + tg];   // 1 line/lane, off-chain
        if (mk) {
            escore += emtag;
            if (t_l > 0) tscore += tr_s[tp * Kc + tg];
        }

        for (int jj = 0; jj < 32; jj += 4) {
            const int tb = ch * 32 + jj;

            // delayed renorm: sample lane0's p at block start; apply at end.
            // exact identity (cacc += log b, p *= 1/b) -> mask-safe.
            float bc = __shfl_sync(FULLM, p, 0);
            float r  = __fdividef(1.0f, bc);
            float lb = __logf(bc);

            float q0 = nxt0, q1 = nxt1, q2 = nxt2, q3 = nxt3;
            // prefetch + exp for t+4..t+7 (clamped; harmless reload)
            int t4 = min(tb + 4, Tc - 1);
            int t5 = min(tb + 5, Tc - 1);
            int t6 = min(tb + 6, Tc - 1);
            int t7 = min(tb + 7, Tc - 1);
            nxt0 = __expf(emB[t4 * Kc + lane]);
            nxt1 = __expf(emB[t5 * Kc + lane]);
            nxt2 = __expf(emB[t6 * Kc + lane]);
            nxt3 = __expf(emB[t7 * Kc + lane]);

            float qa[4] = {q0, q1, q2, q3};
#pragma unroll
            for (int qi = 0; qi < 4; qi++) {
                const int t = tb + qi;
                if (t != 0) {
                    float s0 = 0.f, s1 = 0.f, s2 = 0.f, s3 = 0.f;
#pragma unroll
                    for (int i = 0; i < Kc; i += 4) {
                        s0 = fmaf(__shfl_sync(FULLM, p, i + 0), E[i + 0], s0);
                        s1 = fmaf(__shfl_sync(FULLM, p, i + 1), E[i + 1], s1);
                        s2 = fmaf(__shfl_sync(FULLM, p, i + 2), E[i + 2], s2);
                        s3 = fmaf(__shfl_sync(FULLM, p, i + 3), E[i + 3], s3);
                    }
                    float s  = (s0 + s1) + (s2 + s3);
                    float pn = s * qa[qi];
                    bool  m  = (mbits >> (jj + qi)) & 1u;
                    p = m ? pn : p;
                }
            }

            p    *= r;      // only in-chain renorm cost: 1 FMUL / 4 steps
            cacc += lb;
        }
    }

    // ---- final: logz = cacc + log(sum_j p_j) ----
    float ps = p;
#pragma unroll
    for (int o = 16; o; o >>= 1)
        ps += __shfl_xor_sync(FULLM, ps, o);
    float logz = cacc + __logf(ps);

    if (lane == 0)
        g_partial[b] = logz - escore - tscore;
}

__global__ void __launch_bounds__(256)
crf_reduce(float* __restrict__ out)
{
    __shared__ float sh[8];
    int tid = threadIdx.x;
    float s = 0.f;
    for (int i = tid; i < Bc; i += 256)
        s += g_partial[i];
#pragma unroll
    for (int o = 16; o; o >>= 1)
        s += __shfl_xor_sync(FULLM, s, o);
    if ((tid & 31) == 0) sh[tid >> 5] = s;
    __syncthreads();
    if (tid < 32) {
        float v = (tid < 8) ? sh[tid] : 0.f;
#pragma unroll
        for (int o = 4; o; o >>= 1)
            v += __shfl_xor_sync(FULLM, v, o);
        if (tid == 0) out[0] = v * (1.0f / (float)Bc);
    }
}

extern "C" void kernel_launch(void* const* d_in, const int* in_sizes, int n_in,
                              void* d_out, int out_size)
{
    const float* em    = (const float*)d_in[0];
    const int*   tags  = (const int*)d_in[1];
    const int*   mask  = (const int*)d_in[2];
    const float* trans = (const float*)d_in[3];
    float*       out   = (float*)d_out;

    crf_forward<<<Bc / 8, 256>>>(em, tags, mask, trans);
    crf_reduce<<<1, 256>>>(out);
}

// round 10
// speedup vs baseline: 1.6824x; 1.6824x over previous
#include <cuda_runtime.h>

// CRF forward loss: B=1024, T=512, K=32.
// inputs: emissions f32 [B,T,K], tags i32 [B,T], mask int32 [B,T], trans f32 [K,K]
// output: scalar f32 loss = mean_b( log_z - em_score - tr_score )
//
// R10: R8's log-space per-step math (accurate), shuffles replaced by smem:
//   lane j owns state j; E[i] = exp(trans[i][j]) in regs (column j).
//   step: p = exp(a); STS p; syncwarp; 8x LDS.128 broadcast; 32 FFMA;
//         v = log(s) + em[t][j]; a = mask ? v : a.
//   Renorm (exact uniform shift) once per 4-step block: a -= a0, cacc += a0.
//   Path scores lane-parallel per 32-step chunk (ballot + gathers).
//   Final mean fused via last-block reduction (atomicInc wrap counter).

#define FULLM 0xffffffffu

constexpr int Bc = 1024;
constexpr int Tc = 512;
constexpr int Kc = 32;

__device__ float    g_partial[Bc];
__device__ unsigned g_ctr = 0;   // wraps back to 0 every launch -> replay-safe

__global__ void __launch_bounds__(256, 1)
crf_forward(const float* __restrict__ em,
            const int* __restrict__ tags,
            const int* __restrict__ mask,
            const float* __restrict__ trans,
            float* __restrict__ out)
{
    __shared__ float tr_s[Kc * Kc];
    __shared__ float pbuf[8][2][Kc];   // per-warp double-buffered p vector
    __shared__ float red[8];
    __shared__ int   sdone;

    const int lane = threadIdx.x & 31;
    const int wid  = threadIdx.x >> 5;

    for (int i = threadIdx.x; i < Kc * Kc; i += 256)
        tr_s[i] = trans[i];
    __syncthreads();

    const int b = blockIdx.x * 8 + wid;

    // lane j holds column j of E = exp(transitions)
    float E[Kc];
#pragma unroll
    for (int i = 0; i < Kc; i++)
        E[i] = __expf(tr_s[i * Kc + lane]);

    const float* emB = em   + (size_t)b * Tc * Kc;
    const int*   tgB = tags + (size_t)b * Tc;
    const int*   mB  = mask + (size_t)b * Tc;

    // ---- init: alpha0 = em[0];  a = em0 - em0[0], cacc = em0[0] ----
    float em0 = emB[lane];
    float v00 = __shfl_sync(FULLM, em0, 0);
    float cacc = v00;
    float a    = em0 - v00;

    // prefetch ring: raw em rows t..t+3
    float nxt0 = emB[0 * Kc + lane];
    float nxt1 = emB[1 * Kc + lane];
    float nxt2 = emB[2 * Kc + lane];
    float nxt3 = emB[3 * Kc + lane];

    float escore = 0.f, tscore = 0.f;
    int   tg_carry = 0;

    for (int ch = 0; ch < Tc / 32; ch++) {
        // ---- lane-parallel path scores for this 32-step chunk ----
        const int t_l = ch * 32 + lane;
        int tg = tgB[t_l];
        int mk = mB[t_l];
        unsigned mbits = __ballot_sync(FULLM, mk != 0);
        int tp = __shfl_up_sync(FULLM, tg, 1);
        if (lane == 0) tp = tg_carry;
        tg_carry = __shfl_sync(FULLM, tg, 31);
        float emtag = emB[(size_t)t_l * Kc + tg];
        if (mk) {
            escore += emtag;
            if (t_l > 0) tscore += tr_s[tp * Kc + tg];
        }

        for (int jj = 0; jj < 32; jj += 4) {
            const int tb = ch * 32 + jj;

            // exact uniform-shift renorm, once per 4 steps (mask-safe)
            float v0s = __shfl_sync(FULLM, a, 0);
            a    -= v0s;
            cacc += v0s;

            float e0 = nxt0, e1 = nxt1, e2 = nxt2, e3 = nxt3;
            int t4 = min(tb + 4, Tc - 1);
            int t5 = min(tb + 5, Tc - 1);
            int t6 = min(tb + 6, Tc - 1);
            int t7 = min(tb + 7, Tc - 1);
            nxt0 = emB[t4 * Kc + lane];
            nxt1 = emB[t5 * Kc + lane];
            nxt2 = emB[t6 * Kc + lane];
            nxt3 = emB[t7 * Kc + lane];

            float eq[4] = {e0, e1, e2, e3};
#pragma unroll
            for (int q = 0; q < 4; q++) {
                const int t = tb + q;
                if (t != 0) {
                    float p = __expf(a);
                    pbuf[wid][t & 1][lane] = p;      // STS.32, banks distinct
                    __syncwarp();
                    const float4* pb =
                        reinterpret_cast<const float4*>(pbuf[wid][t & 1]);
                    float4 x0 = pb[0], x1 = pb[1], x2 = pb[2], x3 = pb[3];
                    float4 x4 = pb[4], x5 = pb[5], x6 = pb[6], x7 = pb[7];

                    float s0 = x0.x * E[0];
                    float s1 = x0.y * E[1];
                    float s2 = x0.z * E[2];
                    float s3 = x0.w * E[3];
                    s0 = fmaf(x1.x, E[4],  s0); s1 = fmaf(x1.y, E[5],  s1);
                    s2 = fmaf(x1.z, E[6],  s2); s3 = fmaf(x1.w, E[7],  s3);
                    s0 = fmaf(x2.x, E[8],  s0); s1 = fmaf(x2.y, E[9],  s1);
                    s2 = fmaf(x2.z, E[10], s2); s3 = fmaf(x2.w, E[11], s3);
                    s0 = fmaf(x3.x, E[12], s0); s1 = fmaf(x3.y, E[13], s1);
                    s2 = fmaf(x3.z, E[14], s2); s3 = fmaf(x3.w, E[15], s3);
                    s0 = fmaf(x4.x, E[16], s0); s1 = fmaf(x4.y, E[17], s1);
                    s2 = fmaf(x4.z, E[18], s2); s3 = fmaf(x4.w, E[19], s3);
                    s0 = fmaf(x5.x, E[20], s0); s1 = fmaf(x5.y, E[21], s1);
                    s2 = fmaf(x5.z, E[22], s2); s3 = fmaf(x5.w, E[23], s3);
                    s0 = fmaf(x6.x, E[24], s0); s1 = fmaf(x6.y, E[25], s1);
                    s2 = fmaf(x6.z, E[26], s2); s3 = fmaf(x6.w, E[27], s3);
                    s0 = fmaf(x7.x, E[28], s0); s1 = fmaf(x7.y, E[29], s1);
                    s2 = fmaf(x7.z, E[30], s2); s3 = fmaf(x7.w, E[31], s3);

                    float s = (s0 + s1) + (s2 + s3);
                    float v = __logf(s) + eq[q];
                    bool  m = (mbits >> (jj + q)) & 1u;
                    a = m ? v : a;
                }
            }
        }
    }

    // ---- final logsumexp over states ----
    float amax = a;
#pragma unroll
    for (int o = 16; o; o >>= 1)
        amax = fmaxf(amax, __shfl_xor_sync(FULLM, amax, o));
    float es = __expf(a - amax);
#pragma unroll
    for (int o = 16; o; o >>= 1)
        es += __shfl_xor_sync(FULLM, es, o);
    float logz = cacc + amax + __logf(es);

    if (lane == 0)
        __stcg(&g_partial[b], logz - escore - tscore);

    // ---- fused mean: last block to arrive reduces all partials ----
    __syncthreads();
    if (threadIdx.x == 0) {
        __threadfence();
        unsigned r = atomicInc(&g_ctr, (unsigned)gridDim.x - 1);
        sdone = (r == gridDim.x - 1) ? 1 : 0;
    }
    __syncthreads();
    if (sdone) {
        float s = 0.f;
        for (int i = threadIdx.x; i < Bc; i += 256)
            s += __ldcg(&g_partial[i]);
#pragma unroll
        for (int o = 16; o; o >>= 1)
            s += __shfl_xor_sync(FULLM, s, o);
        if (lane == 0) red[wid] = s;
        __syncthreads();
        if (threadIdx.x < 32) {
            float v = (threadIdx.x < 8) ? red[threadIdx.x] : 0.f;
#pragma unroll
            for (int o = 4; o; o >>= 1)
                v += __shfl_xor_sync(FULLM, v, o);
            if (threadIdx.x == 0)
                out[0] = v * (1.0f / (float)Bc);
        }
    }
}

extern "C" void kernel_launch(void* const* d_in, const int* in_sizes, int n_in,
                              void* d_out, int out_size)
{
    const float* em    = (const float*)d_in[0];
    const int*   tags  = (const int*)d_in[1];
    const int*   mask  = (const int*)d_in[2];
    const float* trans = (const float*)d_in[3];
    float*       out   = (float*)d_out;

    crf_forward<<<Bc / 8, 256>>>(em, tags, mask, trans, out);
}